// round 12
// baseline (speedup 1.0000x reference)
#include <cuda_runtime.h>
#include <cuda_fp16.h>
#include <math.h>
#include <stdint.h>

// Problem constants
static constexpr int Bc   = 8;
static constexpr int Nn   = 10000;
static constexpr int Ee   = 320000;
static constexpr int HISTc = 24;
static constexpr int PREDc = 12;
static constexpr int TT   = HISTc + PREDc;   // 36
static constexpr int HIDc = 64;

// ---------------- device scratch (static, no allocations) ----------------
__device__ __align__(16) __half d_hbuf_s[(long long)Bc * Ee * 32]; // messages, src-sorted
__device__ __align__(16) float d_agg[(long long)Bc * Nn * 32];     // tgt-side partial sums
__device__ __align__(16) __half d_us[Bc * Nn * 32];  // per-node W1s^T x + b1 (fp16)
__device__ __align__(16) __half d_ut[Bc * Nn * 32];  // per-node W1t^T x (fp16)
__device__ __align__(16) float d_h[Bc * Nn * HIDc];   // GRU hidden state
__device__ float d_xn[Bc * Nn];         // current node scalar
__device__ float d_ea[Ee];              // normalized edge attr (original order)
__device__ float d_stats[2];
__device__ int d_deg_t[Nn], d_deg_s[Nn];
__device__ int d_off_t[Nn + 1], d_off_s[Nn + 1];
__device__ int d_cnt_t[Nn], d_cnt_s[Nn];
__device__ int d_sslot_t[Ee];           // t-order slot -> s-order slot
__device__ int d_src_t[Ee], d_tgt_t[Ee];// node ids in t-order
__device__ float d_ea_t[Ee];            // edge attr in t-order
__device__ __align__(16) float2 d_wihT2[30 * 96];  // paired GRU input weights
__device__ __align__(16) float2 d_whhT2[64 * 96];  // paired GRU hidden weights
__device__ unsigned int d_bar_cnt;
__device__ volatile unsigned int d_bar_flag;

// ---------------- helpers ----------------
__device__ __forceinline__ float sigm(float x) {
    return __fdividef(1.0f, 1.0f + __expf(-x));
}
__device__ __forceinline__ float sigm_fast(float x) {
    float y = 0.5f * x;
    float tv;
    asm("tanh.approx.f32 %0, %1;" : "=f"(tv) : "f"(y));
    return fmaf(0.5f, tv, 0.5f);
}
__device__ __forceinline__ float tanh_f(float x) {
    x = fminf(15.0f, fmaxf(-15.0f, x));
    float e = __expf(-2.0f * x);
    return __fdividef(1.0f - e, 1.0f + e);
}
__device__ __forceinline__ unsigned long long splat2(float x) {
    unsigned long long r;
    asm("mov.b64 %0, {%1, %1};" : "=l"(r) : "f"(x));
    return r;
}
__device__ __forceinline__ unsigned long long pack2(float lo, float hi) {
    unsigned long long r;
    asm("mov.b64 %0, {%1, %2};" : "=l"(r) : "f"(lo), "f"(hi));
    return r;
}
__device__ __forceinline__ void fma2(unsigned long long& d, unsigned long long a, unsigned long long b) {
    asm("fma.rn.f32x2 %0, %1, %2, %0;" : "+l"(d) : "l"(a), "l"(b));
}
__device__ __forceinline__ float2 unpack2(unsigned long long v) {
    float2 f;
    asm("mov.b64 {%0, %1}, %2;" : "=f"(f.x), "=f"(f.y) : "l"(v));
    return f;
}
__device__ __forceinline__ uint32_t smem_u32(const void* p) {
    return (uint32_t)__cvta_generic_to_shared(p);
}

// ---------------- grid barrier (setup only) ----------------
__device__ __forceinline__ void grid_bar(unsigned int phase, int nblocks) {
    __syncthreads();
    if (threadIdx.x == 0) {
        __threadfence();
        unsigned int old = atomicAdd(&d_bar_cnt, 1u);
        if (old == (unsigned)nblocks - 1u) {
            d_bar_cnt = 0u;
            __threadfence();
            d_bar_flag = phase;
        } else {
            while (d_bar_flag < phase) __nanosleep(60);
            __threadfence();
        }
    }
    __syncthreads();
}

__global__ void reset_bar_kernel() {
    if (threadIdx.x == 0) { d_bar_cnt = 0u; *(unsigned int*)&d_bar_flag = 0u; }
}

// ---------------- fused setup kernel (persistent, 132 blocks x 256) --------
static constexpr int SETUP_BLOCKS = 132;

__global__ void __launch_bounds__(256) setup_kernel(
    const float* __restrict__ t2m, const float* __restrict__ ea,
    const int* __restrict__ ei,
    const float* __restrict__ wih, const float* __restrict__ whh)
{
    const int g = blockIdx.x * 256 + threadIdx.x;
    const int NT = SETUP_BLOCKS * 256;
    __shared__ float ssum[256], ssq[256];

    if (g < 2) d_stats[g] = 0.f;
    for (int i = g; i < Nn; i += NT) { d_deg_t[i] = 0; d_deg_s[i] = 0; d_cnt_t[i] = 0; d_cnt_s[i] = 0; }
    for (int i = g; i < Bc * Nn; i += NT) {
        int b = i / Nn, n = i - b * Nn;
        d_xn[i] = t2m[((long long)b * HISTc + (HISTc - 1)) * Nn + n];
    }
    for (long long j = g; j < (long long)Bc * Nn * HIDc; j += NT) d_h[j] = 0.f;
    for (long long j = g; j < (long long)Bc * Nn * 32; j += NT) d_agg[j] = 0.f;
    for (int i = g; i < 30 * 96; i += NT) {
        int k = i / 96, c = i - k * 96;
        int gg = c / 32, j = c - gg * 32;
        d_wihT2[i] = make_float2(wih[(gg * 64 + j) * 30 + k], wih[(gg * 64 + 32 + j) * 30 + k]);
    }
    for (int i = g; i < 64 * 96; i += NT) {
        int k = i / 96, c = i - k * 96;
        int gg = c / 32, j = c - gg * 32;
        d_whhT2[i] = make_float2(whh[(gg * 64 + j) * 64 + k], whh[(gg * 64 + 32 + j) * 64 + k]);
    }
    grid_bar(1, SETUP_BLOCKS);

    {
        float lsum = 0.f, lsq = 0.f;
        for (int i = g; i < Ee; i += NT) {
            float v = ea[i];
            lsum += v; lsq += v * v;
            atomicAdd(&d_deg_s[ei[i]], 1);
            atomicAdd(&d_deg_t[ei[Ee + i]], 1);
        }
        int t = threadIdx.x;
        ssum[t] = lsum; ssq[t] = lsq;
        __syncthreads();
        for (int s = 128; s > 0; s >>= 1) {
            if (t < s) { ssum[t] += ssum[t + s]; ssq[t] += ssq[t + s]; }
            __syncthreads();
        }
        if (t == 0) {
            atomicAdd(&d_stats[0], ssum[0]);
            atomicAdd(&d_stats[1], ssq[0]);
        }
    }
    grid_bar(2, SETUP_BLOCKS);

    if (blockIdx.x < 2) {
        int which = blockIdx.x;
        const int* deg = which ? d_deg_s : d_deg_t;
        int* off = which ? d_off_s : d_off_t;
        __shared__ int part[256];
        const int CH = (Nn + 255) / 256;
        int t = threadIdx.x;
        int s = 0;
        for (int i = 0; i < CH; i++) {
            int idx = t * CH + i;
            if (idx < Nn) s += deg[idx];
        }
        part[t] = s;
        __syncthreads();
        if (t == 0) {
            int run = 0;
            for (int i = 0; i < 256; i++) { int vv = part[i]; part[i] = run; run += vv; }
            off[Nn] = run;
        }
        __syncthreads();
        int run = part[t];
        for (int i = 0; i < CH; i++) {
            int idx = t * CH + i;
            if (idx < Nn) { off[idx] = run; run += deg[idx]; }
        }
    } else {
        float s = d_stats[0], sq = d_stats[1];
        float mean = s / (float)Ee;
        float var = (sq - s * s / (float)Ee) / (float)(Ee - 1);
        float inv = rsqrtf(var);
        int gg = (blockIdx.x - 2) * 256 + threadIdx.x;
        for (int i = gg; i < Ee; i += (SETUP_BLOCKS - 2) * 256)
            d_ea[i] = (ea[i] - mean) * inv;
    }
    grid_bar(3, SETUP_BLOCKS);

    for (int e = g; e < Ee; e += NT) {
        int sn = ei[e], tn = ei[Ee + e];
        int ps = atomicAdd(&d_cnt_s[sn], 1);
        int sslot = d_off_s[sn] + ps;
        int pt = atomicAdd(&d_cnt_t[tn], 1);
        int tslot = d_off_t[tn] + pt;
        d_sslot_t[tslot] = sslot;
        d_src_t[tslot] = sn;
        d_tgt_t[tslot] = tn;
        d_ea_t[tslot] = d_ea[e];
    }
}

// ---------------- per-node layer-1 precompute ----------------
__global__ void __launch_bounds__(256) upre_kernel(
    const float* __restrict__ feat,
    const float* __restrict__ w1, const float* __restrict__ b1, int t)
{
    __shared__ float sw[34 * 32];
    __shared__ float sb[32];
    for (int i = threadIdx.x; i < 34 * 32; i += 256) sw[i] = w1[i];
    if (threadIdx.x < 32) sb[threadIdx.x] = b1[threadIdx.x];
    __syncthreads();

    int row = blockIdx.x * 256 + threadIdx.x;
    if (row >= Bc * Nn) return;
    int b = row / Nn, n = row - b * Nn;

    float x[17];
    x[0] = d_xn[row];
    {
        const float4* fs = (const float4*)(feat + ((long long)(b * TT + HISTc + t) * Nn + n) * 16);
        float4 f0 = fs[0], f1 = fs[1], f2 = fs[2], f3 = fs[3];
        x[1] = f0.x; x[2] = f0.y; x[3] = f0.z; x[4] = f0.w;
        x[5] = f1.x; x[6] = f1.y; x[7] = f1.z; x[8] = f1.w;
        x[9] = f2.x; x[10] = f2.y; x[11] = f2.z; x[12] = f2.w;
        x[13] = f3.x; x[14] = f3.y; x[15] = f3.z; x[16] = f3.w;
    }

    float us[32], ut[32];
    #pragma unroll
    for (int j = 0; j < 32; j++) { us[j] = sb[j]; ut[j] = 0.f; }
    #pragma unroll
    for (int k = 0; k < 17; k++) {
        float xk = x[k];
        const float* ws = sw + k * 32;
        const float* wt = sw + (17 + k) * 32;
        #pragma unroll
        for (int j = 0; j < 32; j++) {
            us[j] = fmaf(xk, ws[j], us[j]);
            ut[j] = fmaf(xk, wt[j], ut[j]);
        }
    }
    uint32_t ps[16], pt[16];
    #pragma unroll
    for (int j = 0; j < 16; j++) {
        __half2 hs = __floats2half2_rn(us[2 * j], us[2 * j + 1]);
        __half2 ht = __floats2half2_rn(ut[2 * j], ut[2 * j + 1]);
        ps[j] = *(uint32_t*)&hs;
        pt[j] = *(uint32_t*)&ht;
    }
    uint4* dus = (uint4*)(d_us + (long long)row * 32);
    uint4* dut = (uint4*)(d_ut + (long long)row * 32);
    const uint4* psv = (const uint4*)ps;
    const uint4* ptv = (const uint4*)pt;
    #pragma unroll
    for (int q = 0; q < 4; q++) { dus[q] = psv[q]; dut[q] = ptv[q]; }
}

// ---------------- edge kernel: coop gather + HMMA + segmented t-reduce -----
// 128 threads = 4 warps; warp owns 32 consecutive t-slots. 1 edge per thread.
__global__ void __launch_bounds__(128) edge_kernel(
    const float* __restrict__ w1,
    const float* __restrict__ w2, const float* __restrict__ b2)
{
    __shared__ __align__(16) uint4 smA[4][128];   // message tile (swizzled)
    __shared__ __align__(16) uint4 smU[4][160];   // u_s stage, row stride 5
    __shared__ int s_tn[4][32];                   // tgt ids per warp
    __shared__ float s_w2[32 * 30];
    __shared__ float s_b2[32];
    __shared__ float s_wea[32];

    for (int i = threadIdx.x; i < 32 * 30; i += 128) s_w2[i] = w2[i];
    if (threadIdx.x < 32) {
        s_b2[threadIdx.x] = (threadIdx.x < 30) ? b2[threadIdx.x] : 0.f;
        s_wea[threadIdx.x] = w1[34 * 32 + threadIdx.x];
    }
    __syncthreads();

    int lane = threadIdx.x & 31;
    int w = threadIdx.x >> 5;
    int b = blockIdx.y;
    int base = blockIdx.x * 128 + w * 32;    // warp's first t-slot
    int idx = base + lane;

    // ---- B fragments + bias ----
    int kk = (lane & 3) * 2;
    int nn = lane >> 2;
    uint32_t bfr[4][2][2];
    float bias0[4], bias1[4];
    #pragma unroll
    for (int ni = 0; ni < 4; ni++) {
        int n0 = ni * 8 + nn;
        #pragma unroll
        for (int ki = 0; ki < 2; ki++) {
            int k0 = ki * 16 + kk;
            float f0 = (n0 < 30) ? s_w2[k0 * 30 + n0] : 0.f;
            float f1 = (n0 < 30) ? s_w2[(k0 + 1) * 30 + n0] : 0.f;
            float f2 = (n0 < 30) ? s_w2[(k0 + 8) * 30 + n0] : 0.f;
            float f3 = (n0 < 30) ? s_w2[(k0 + 9) * 30 + n0] : 0.f;
            __half2 h01 = __floats2half2_rn(f0, f1);
            __half2 h23 = __floats2half2_rn(f2, f3);
            bfr[ni][ki][0] = *(uint32_t*)&h01;
            bfr[ni][ki][1] = *(uint32_t*)&h23;
        }
        int c = ni * 8 + kk;
        bias0[ni] = s_b2[c];
        bias1[ni] = s_b2[c + 1];
    }

    int sn = d_src_t[idx], tn = d_tgt_t[idx];
    int ss = d_sslot_t[idx];
    float eav = d_ea_t[idx];
    s_tn[w][lane] = tn;

    // ---- cooperative u_s gather: 4 instr, 8 segments each ----
    {
        int j = lane & 3;          // 16B chunk
        int esub = lane >> 2;      // 0..7
        #pragma unroll
        for (int it = 0; it < 4; it++) {
            int e = it * 8 + esub;
            int sn_e = __shfl_sync(0xffffffffu, sn, e);
            smU[w][e * 5 + j] = ((const uint4*)(d_us + ((long long)b * Nn + sn_e) * 32))[j];
        }
    }
    // u_t per-thread (tgt-sorted: broadcast-heavy, cheap)
    uint4 utv[4];
    {
        const uint4* up = (const uint4*)(d_ut + ((long long)b * Nn + tn) * 32);
        #pragma unroll
        for (int q = 0; q < 4; q++) utv[q] = up[q];
    }
    __syncwarp();

    // ---- layer 1: read own u_s row from stage, sigmoid, pack fp16 ----
    uint4 hrow[4];
    #pragma unroll
    for (int q = 0; q < 4; q++) {
        uint4 va = smU[w][lane * 5 + q];
        uint4 vb = utv[q];
        const __half2* ha = (const __half2*)&va;
        const __half2* hb = (const __half2*)&vb;
        uint32_t packed[4];
        #pragma unroll
        for (int p = 0; p < 4; p++) {
            float2 fa = __half22float2(ha[p]);
            float2 fb = __half22float2(hb[p]);
            int c = q * 8 + p * 2;
            float v0 = sigm_fast(fmaf(eav, s_wea[c],     fa.x + fb.x));
            float v1 = sigm_fast(fmaf(eav, s_wea[c + 1], fa.y + fb.y));
            __half2 hv = __floats2half2_rn(v0, v1);
            packed[p] = *(uint32_t*)&hv;
        }
        hrow[q] = *(uint4*)packed;
    }

    // ---- STS h1 into swizzled tile ----
    {
        int sw = (lane >> 1) & 3;
        #pragma unroll
        for (int j = 0; j < 4; j++)
            smA[w][lane * 4 + (j ^ sw)] = hrow[j];
    }
    __syncwarp();

    // ---- ldmatrix A fragments ----
    uint32_t afr[2][2][4];
    {
        int grp = lane >> 3;
        int lr = lane & 7;
        #pragma unroll
        for (int mi = 0; mi < 2; mi++) {
            #pragma unroll
            for (int ki = 0; ki < 2; ki++) {
                int row = mi * 16 + ((grp & 1) ? 8 : 0) + lr;
                int chunk = ki * 2 + (grp >> 1);
                int phys = row * 4 + (chunk ^ ((row >> 1) & 3));
                uint32_t addr = smem_u32(&smA[w][phys]);
                asm volatile("ldmatrix.sync.aligned.m8n8.x4.shared.b16 {%0,%1,%2,%3}, [%4];"
                             : "=r"(afr[mi][ki][0]), "=r"(afr[mi][ki][1]),
                               "=r"(afr[mi][ki][2]), "=r"(afr[mi][ki][3])
                             : "r"(addr));
            }
        }
    }

    // ---- 16 MMAs ----
    float dacc[2][4][4];
    #pragma unroll
    for (int mi = 0; mi < 2; mi++)
        #pragma unroll
        for (int ni = 0; ni < 4; ni++)
            #pragma unroll
            for (int p = 0; p < 4; p++) dacc[mi][ni][p] = 0.f;
    #pragma unroll
    for (int mi = 0; mi < 2; mi++) {
        #pragma unroll
        for (int ni = 0; ni < 4; ni++) {
            #pragma unroll
            for (int ki = 0; ki < 2; ki++) {
                asm volatile(
                    "mma.sync.aligned.m16n8k16.row.col.f32.f16.f16.f32 "
                    "{%0,%1,%2,%3}, {%4,%5,%6,%7}, {%8,%9}, {%0,%1,%2,%3};"
                    : "+f"(dacc[mi][ni][0]), "+f"(dacc[mi][ni][1]),
                      "+f"(dacc[mi][ni][2]), "+f"(dacc[mi][ni][3])
                    : "r"(afr[mi][ki][0]), "r"(afr[mi][ki][1]),
                      "r"(afr[mi][ki][2]), "r"(afr[mi][ki][3]),
                      "r"(bfr[ni][ki][0]), "r"(bfr[ni][ki][1]));
            }
        }
    }
    __syncwarp();

    // ---- epilogue: bias + sigmoid -> swizzled tile ----
    {
        uint32_t* u = (uint32_t*)&smA[w][0];
        int gr = lane >> 2;
        #pragma unroll
        for (int mi = 0; mi < 2; mi++) {
            #pragma unroll
            for (int ni = 0; ni < 4; ni++) {
                float v0 = sigm_fast(dacc[mi][ni][0] + bias0[ni]);
                float v1 = sigm_fast(dacc[mi][ni][1] + bias1[ni]);
                float v2 = sigm_fast(dacc[mi][ni][2] + bias0[ni]);
                float v3 = sigm_fast(dacc[mi][ni][3] + bias1[ni]);
                __half2 h01 = __floats2half2_rn(v0, v1);
                __half2 h23 = __floats2half2_rn(v2, v3);
                int row0 = mi * 16 + gr;
                int row1 = row0 + 8;
                int c0 = ni ^ ((row0 >> 1) & 3);
                int c1 = ni ^ ((row1 >> 1) & 3);
                u[(row0 * 4 + c0) * 4 + (lane & 3)] = *(uint32_t*)&h01;
                u[(row1 * 4 + c1) * 4 + (lane & 3)] = *(uint32_t*)&h23;
            }
        }
    }
    __syncwarp();

    // ---- segmented t-side reduction: lane = channel, flush on tgt change ----
    {
        float acc = 0.f;
        int cur = s_tn[w][0];
        int ch_hi = lane >> 3;     // which uint4 chunk holds this channel
        int ch_lo = lane & 7;      // half index within chunk
        #pragma unroll
        for (int e = 0; e < 32; e++) {
            int phys = e * 4 + (ch_hi ^ ((e >> 1) & 3));
            float v = __half2float(((const __half*)&smA[w][phys])[ch_lo]);
            acc += v;
            int nxt = (e < 31) ? s_tn[w][e + 1] : -1;
            if (nxt != cur) {
                if (lane < 30)
                    atomicAdd(&d_agg[((long long)b * Nn + cur) * 32 + lane], acc);
                acc = 0.f;
                cur = nxt;
            }
        }
    }

    // ---- cooperative s-store from tile: 4 instr, pad zeroed ----
    {
        int j = lane & 3;
        int esub = lane >> 2;
        #pragma unroll
        for (int it = 0; it < 4; it++) {
            int e = it * 8 + esub;
            uint4 v = smA[w][e * 4 + (j ^ ((e >> 1) & 3))];
            if (j == 3) v.w = 0u;    // channels 30,31
            int ss_e = __shfl_sync(0xffffffffu, ss, e);
            ((uint4*)(d_hbuf_s + ((long long)b * Ee + ss_e) * 32))[j] = v;
        }
    }
}

// ---------------- persistent step2: 2 rows per warp ----------------
static constexpr int S2_BLOCKS = 296;
static constexpr int S2_WARPS  = 16;     // 512 threads
static constexpr int TASKS = Bc * Nn / 2;  // 40000

__global__ void __launch_bounds__(512) step2_kernel(
    const float* __restrict__ feat,
    const float* __restrict__ node_w, const float* __restrict__ node_b,
    const float* __restrict__ bih, const float* __restrict__ bhh,
    const float* __restrict__ fcw, const float* __restrict__ fcb,
    float* __restrict__ out, int t)
{
    extern __shared__ float dynw[];
    float2* s_wih2 = (float2*)dynw;                 // [30][96] pairs
    float2* s_whh2 = (float2*)(dynw + 30 * 96 * 2); // [64][96] pairs
    __shared__ __align__(16) float sx[S2_WARPS][2][32];
    __shared__ __align__(16) float sxin[S2_WARPS][2][32];
    __shared__ __align__(16) float sh[S2_WARPS][128];
    __shared__ float s_nw[30 * 13], s_nb[16];

    for (int i = threadIdx.x; i < 30 * 96; i += 512) s_wih2[i] = d_wihT2[i];
    for (int i = threadIdx.x; i < 64 * 96; i += 512) s_whh2[i] = d_whhT2[i];
    for (int i = threadIdx.x; i < 30 * 13; i += 512) s_nw[i] = node_w[i];
    if (threadIdx.x < 13) s_nb[threadIdx.x] = node_b[threadIdx.x];
    __syncthreads();

    int lane = threadIdx.x & 31;
    int w = threadIdx.x >> 5;
    float* shp = sh[w];
    int sub = lane >> 2;

    unsigned long long bih_r = pack2(bih[lane],       bih[32 + lane]);
    unsigned long long bih_z = pack2(bih[64 + lane],  bih[96 + lane]);
    unsigned long long bih_n = pack2(bih[128 + lane], bih[160 + lane]);
    unsigned long long bhh_r = pack2(bhh[lane],       bhh[32 + lane]);
    unsigned long long bhh_z = pack2(bhh[64 + lane],  bhh[96 + lane]);
    unsigned long long bhh_n = pack2(bhh[128 + lane], bhh[160 + lane]);
    float fcw0 = fcw[lane], fcw1 = fcw[32 + lane];
    float fcb0 = fcb[0];

    for (int task = blockIdx.x * S2_WARPS + w; task < TASKS; task += S2_BLOCKS * S2_WARPS) {
        int row0 = task * 2;
        int b = row0 / Nn, n0 = row0 - b * Nn;

        #pragma unroll
        for (int r = 0; r < 2; r++) {
            int n = n0 + r;
            // t-side: read precomputed agg + reset for next step
            long long apos = ((long long)b * Nn + n) * 32 + lane;
            float aggv = d_agg[apos];
            d_agg[apos] = 0.f;

            // s-side: contiguous stream, negated
            float2 acc[4];
            #pragma unroll
            for (int p = 0; p < 4; p++) acc[p] = make_float2(0.f, 0.f);
            {
                int e0 = d_off_s[n], e1 = d_off_s[n + 1];
                int cnt = e1 - e0;
                const uint4* p4 = (const uint4*)(d_hbuf_s + ((long long)b * Ee + e0) * 32);
                int full = cnt >> 3, tail = cnt & 7;
                for (int i = 0; i < full; i++) {
                    uint4 v = p4[i * 32 + lane];
                    const __half2* h = (const __half2*)&v;
                    #pragma unroll
                    for (int p = 0; p < 4; p++) {
                        float2 f = __half22float2(h[p]);
                        acc[p].x -= f.x; acc[p].y -= f.y;
                    }
                }
                if (sub < tail) {
                    uint4 v = p4[full * 32 + lane];
                    const __half2* h = (const __half2*)&v;
                    #pragma unroll
                    for (int p = 0; p < 4; p++) {
                        float2 f = __half22float2(h[p]);
                        acc[p].x -= f.x; acc[p].y -= f.y;
                    }
                }
            }
            #pragma unroll
            for (int p = 0; p < 4; p++) {
                #pragma unroll
                for (int st = 4; st <= 16; st <<= 1) {
                    acc[p].x += __shfl_xor_sync(0xffffffffu, acc[p].x, st);
                    acc[p].y += __shfl_xor_sync(0xffffffffu, acc[p].y, st);
                }
            }
            if (lane < 4) {
                float2* sxf2 = (float2*)sx[w][r];
                #pragma unroll
                for (int p = 0; p < 4; p++) sxf2[lane * 4 + p] = acc[p];
            }
            __syncwarp();
            sx[w][r][lane] += aggv;
        }
        __syncwarp();

        if (lane < 26) {
            int r = (lane >= 13) ? 1 : 0;
            int u = lane - 13 * r;
            float g = s_nb[u];
            #pragma unroll
            for (int k = 0; k < 30; k++) g = fmaf(sx[w][r][k], s_nw[k * 13 + u], g);
            sxin[w][r][u] = sigm(g);
        }
        if (lane < 2) sxin[w][lane][13] = d_xn[row0 + lane];
        #pragma unroll
        for (int r = 0; r < 2; r++) {
            if (lane < 16)
                sxin[w][r][14 + lane] = feat[((long long)(b * TT + HISTc + t) * Nn + n0 + r) * 16 + lane];
        }
        ((float4*)shp)[lane] = ((const float4*)(d_h + (long long)row0 * 64))[lane];
        __syncwarp();

        unsigned long long ar0 = bih_r, az0 = bih_z, an0 = bih_n;
        unsigned long long ar1 = bih_r, az1 = bih_z, an1 = bih_n;
        #pragma unroll
        for (int k = 0; k < 30; k++) {
            const unsigned long long* wr = (const unsigned long long*)(s_wih2 + k * 96);
            unsigned long long wR = wr[lane], wZ = wr[32 + lane], wN = wr[64 + lane];
            unsigned long long x0 = splat2(sxin[w][0][k]);
            unsigned long long x1 = splat2(sxin[w][1][k]);
            fma2(ar0, x0, wR); fma2(az0, x0, wZ); fma2(an0, x0, wN);
            fma2(ar1, x1, wR); fma2(az1, x1, wZ); fma2(an1, x1, wN);
        }
        unsigned long long gr0 = bhh_r, gz0 = bhh_z, gn0 = bhh_n;
        unsigned long long gr1 = bhh_r, gz1 = bhh_z, gn1 = bhh_n;
        #pragma unroll
        for (int k = 0; k < 64; k++) {
            const unsigned long long* wr = (const unsigned long long*)(s_whh2 + k * 96);
            unsigned long long wR = wr[lane], wZ = wr[32 + lane], wN = wr[64 + lane];
            unsigned long long h0 = splat2(shp[k]);
            unsigned long long h1 = splat2(shp[64 + k]);
            fma2(gr0, h0, wR); fma2(gz0, h0, wZ); fma2(gn0, h0, wN);
            fma2(gr1, h1, wR); fma2(gz1, h1, wZ); fma2(gn1, h1, wN);
        }

        {
            float2 fa_r = unpack2(ar0), fa_z = unpack2(az0), fa_n = unpack2(an0);
            float2 fg_r = unpack2(gr0), fg_z = unpack2(gz0), fg_n = unpack2(gn0);
            float hold0 = shp[lane], hold1 = shp[32 + lane];
            float r0 = sigm(fa_r.x + fg_r.x), r1 = sigm(fa_r.y + fg_r.y);
            float z0 = sigm(fa_z.x + fg_z.x), z1 = sigm(fa_z.y + fg_z.y);
            float nn0 = tanh_f(fa_n.x + r0 * fg_n.x), nn1 = tanh_f(fa_n.y + r1 * fg_n.y);
            float hn0 = (1.f - z0) * nn0 + z0 * hold0;
            float hn1 = (1.f - z1) * nn1 + z1 * hold1;
            long long rw = (long long)row0 * 64;
            d_h[rw + lane] = hn0;
            d_h[rw + 32 + lane] = hn1;
            float o = hn0 * fcw0 + hn1 * fcw1;
            #pragma unroll
            for (int off = 16; off > 0; off >>= 1)
                o += __shfl_xor_sync(0xffffffffu, o, off);
            if (lane == 0) {
                float v = o + fcb0;
                d_xn[row0] = v;
                out[((long long)b * PREDc + t) * Nn + n0] = v;
            }
        }
        {
            float2 fa_r = unpack2(ar1), fa_z = unpack2(az1), fa_n = unpack2(an1);
            float2 fg_r = unpack2(gr1), fg_z = unpack2(gz1), fg_n = unpack2(gn1);
            float hold0 = shp[64 + lane], hold1 = shp[96 + lane];
            float r0 = sigm(fa_r.x + fg_r.x), r1 = sigm(fa_r.y + fg_r.y);
            float z0 = sigm(fa_z.x + fg_z.x), z1 = sigm(fa_z.y + fg_z.y);
            float nn0 = tanh_f(fa_n.x + r0 * fg_n.x), nn1 = tanh_f(fa_n.y + r1 * fg_n.y);
            float hn0 = (1.f - z0) * nn0 + z0 * hold0;
            float hn1 = (1.f - z1) * nn1 + z1 * hold1;
            long long rw = (long long)(row0 + 1) * 64;
            d_h[rw + lane] = hn0;
            d_h[rw + 32 + lane] = hn1;
            float o = hn0 * fcw0 + hn1 * fcw1;
            #pragma unroll
            for (int off = 16; off > 0; off >>= 1)
                o += __shfl_xor_sync(0xffffffffu, o, off);
            if (lane == 0) {
                float v = o + fcb0;
                d_xn[row0 + 1] = v;
                out[((long long)b * PREDc + t) * Nn + n0 + 1] = v;
            }
        }
        __syncwarp();
    }
}

// ---------------- launcher ----------------
extern "C" void kernel_launch(void* const* d_in, const int* in_sizes, int n_in,
                              void* d_out, int out_size)
{
    const float* t2m  = (const float*)d_in[0];
    const float* feat = (const float*)d_in[1];
    const int*   ei   = (const int*)d_in[2];
    const float* ea   = (const float*)d_in[3];
    const float* w1   = (const float*)d_in[4];
    const float* b1   = (const float*)d_in[5];
    const float* w2   = (const float*)d_in[6];
    const float* b2   = (const float*)d_in[7];
    const float* nw   = (const float*)d_in[8];
    const float* nb   = (const float*)d_in[9];
    const float* wih  = (const float*)d_in[10];
    const float* whh  = (const float*)d_in[11];
    const float* bih  = (const float*)d_in[12];
    const float* bhh  = (const float*)d_in[13];
    const float* fcw  = (const float*)d_in[14];
    const float* fcb  = (const float*)d_in[15];
    float* out = (float*)d_out;

    const int smem2 = (30 * 96 + 64 * 96) * 2 * (int)sizeof(float);
    cudaFuncSetAttribute(step2_kernel, cudaFuncAttributeMaxDynamicSharedMemorySize, smem2);

    // launches: reset(0), setup(1), upre(2), edge(3) <- ncu profiles index 3
    reset_bar_kernel<<<1, 32>>>();
    setup_kernel<<<SETUP_BLOCKS, 256>>>(t2m, ea, ei, wih, whh);

    dim3 egrid(Ee / 128, Bc);
    for (int t = 0; t < PREDc; t++) {
        upre_kernel<<<(Bc * Nn + 255) / 256, 256>>>(feat, w1, b1, t);
        edge_kernel<<<egrid, 128>>>(w1, w2, b2);
        step2_kernel<<<S2_BLOCKS, 512, smem2>>>(feat, nw, nb, bih, bhh, fcw, fcb, out, t);
    }
}

// round 13
// speedup vs baseline: 1.3841x; 1.3841x over previous
#include <cuda_runtime.h>
#include <cuda_fp16.h>
#include <math.h>
#include <stdint.h>

// Problem constants
static constexpr int Bc   = 8;
static constexpr int Nn   = 10000;
static constexpr int Ee   = 320000;
static constexpr int HISTc = 24;
static constexpr int PREDc = 12;
static constexpr int TT   = HISTc + PREDc;   // 36
static constexpr int HIDc = 64;

// ---------------- device scratch (static, no allocations) ----------------
__device__ __align__(16) __half d_hbuf_t[(long long)Bc * Ee * 32]; // messages, tgt-sorted
__device__ __align__(16) __half d_hbuf_s[(long long)Bc * Ee * 32]; // messages, src-sorted
__device__ __align__(16) __half d_us[Bc * Nn * 32];  // per-node W1s^T x + b1 (fp16)
__device__ __align__(16) __half d_ut[Bc * Nn * 32];  // per-node W1t^T x (fp16)
__device__ __align__(16) float d_h[Bc * Nn * HIDc];   // GRU hidden state
__device__ float d_xn[Bc * Nn];         // current node scalar
__device__ float d_ea[Ee];              // normalized edge attr (original order)
__device__ float d_stats[2];
__device__ int d_deg_t[Nn], d_deg_s[Nn];
__device__ int d_off_t[Nn + 1], d_off_s[Nn + 1];
__device__ int d_cnt_t[Nn], d_cnt_s[Nn];
__device__ int d_sslot_t[Ee];           // t-order slot -> s-order slot
__device__ int d_src_t[Ee], d_tgt_t[Ee];// node ids in t-order
__device__ float d_ea_t[Ee];            // edge attr in t-order
__device__ __align__(16) float2 d_wihT2[30 * 96];  // paired GRU input weights
__device__ __align__(16) float2 d_whhT2[64 * 96];  // paired GRU hidden weights
__device__ unsigned int d_bar_cnt;
__device__ volatile unsigned int d_bar_flag;

// ---------------- helpers ----------------
__device__ __forceinline__ float sigm(float x) {
    return __fdividef(1.0f, 1.0f + __expf(-x));
}
__device__ __forceinline__ float sigm_fast(float x) {
    float y = 0.5f * x;
    float tv;
    asm("tanh.approx.f32 %0, %1;" : "=f"(tv) : "f"(y));
    return fmaf(0.5f, tv, 0.5f);
}
__device__ __forceinline__ float tanh_f(float x) {
    x = fminf(15.0f, fmaxf(-15.0f, x));
    float e = __expf(-2.0f * x);
    return __fdividef(1.0f - e, 1.0f + e);
}
__device__ __forceinline__ unsigned long long splat2(float x) {
    unsigned long long r;
    asm("mov.b64 %0, {%1, %1};" : "=l"(r) : "f"(x));
    return r;
}
__device__ __forceinline__ unsigned long long pack2(float lo, float hi) {
    unsigned long long r;
    asm("mov.b64 %0, {%1, %2};" : "=l"(r) : "f"(lo), "f"(hi));
    return r;
}
__device__ __forceinline__ void fma2(unsigned long long& d, unsigned long long a, unsigned long long b) {
    asm("fma.rn.f32x2 %0, %1, %2, %0;" : "+l"(d) : "l"(a), "l"(b));
}
__device__ __forceinline__ float2 unpack2(unsigned long long v) {
    float2 f;
    asm("mov.b64 {%0, %1}, %2;" : "=f"(f.x), "=f"(f.y) : "l"(v));
    return f;
}
__device__ __forceinline__ uint32_t smem_u32(const void* p) {
    return (uint32_t)__cvta_generic_to_shared(p);
}

// ---------------- grid barrier (setup only) ----------------
__device__ __forceinline__ void grid_bar(unsigned int phase, int nblocks) {
    __syncthreads();
    if (threadIdx.x == 0) {
        __threadfence();
        unsigned int old = atomicAdd(&d_bar_cnt, 1u);
        if (old == (unsigned)nblocks - 1u) {
            d_bar_cnt = 0u;
            __threadfence();
            d_bar_flag = phase;
        } else {
            while (d_bar_flag < phase) __nanosleep(60);
            __threadfence();
        }
    }
    __syncthreads();
}

__global__ void reset_bar_kernel() {
    if (threadIdx.x == 0) { d_bar_cnt = 0u; *(unsigned int*)&d_bar_flag = 0u; }
}

// ---------------- fused setup kernel (persistent, 132 blocks x 256) --------
static constexpr int SETUP_BLOCKS = 132;

__global__ void __launch_bounds__(256) setup_kernel(
    const float* __restrict__ t2m, const float* __restrict__ ea,
    const int* __restrict__ ei,
    const float* __restrict__ wih, const float* __restrict__ whh)
{
    const int g = blockIdx.x * 256 + threadIdx.x;
    const int NT = SETUP_BLOCKS * 256;
    __shared__ float ssum[256], ssq[256];

    if (g < 2) d_stats[g] = 0.f;
    for (int i = g; i < Nn; i += NT) { d_deg_t[i] = 0; d_deg_s[i] = 0; d_cnt_t[i] = 0; d_cnt_s[i] = 0; }
    for (int i = g; i < Bc * Nn; i += NT) {
        int b = i / Nn, n = i - b * Nn;
        d_xn[i] = t2m[((long long)b * HISTc + (HISTc - 1)) * Nn + n];
    }
    for (long long j = g; j < (long long)Bc * Nn * HIDc; j += NT) d_h[j] = 0.f;
    for (int i = g; i < 30 * 96; i += NT) {
        int k = i / 96, c = i - k * 96;
        int gg = c / 32, j = c - gg * 32;
        d_wihT2[i] = make_float2(wih[(gg * 64 + j) * 30 + k], wih[(gg * 64 + 32 + j) * 30 + k]);
    }
    for (int i = g; i < 64 * 96; i += NT) {
        int k = i / 96, c = i - k * 96;
        int gg = c / 32, j = c - gg * 32;
        d_whhT2[i] = make_float2(whh[(gg * 64 + j) * 64 + k], whh[(gg * 64 + 32 + j) * 64 + k]);
    }
    grid_bar(1, SETUP_BLOCKS);

    {
        float lsum = 0.f, lsq = 0.f;
        for (int i = g; i < Ee; i += NT) {
            float v = ea[i];
            lsum += v; lsq += v * v;
            atomicAdd(&d_deg_s[ei[i]], 1);
            atomicAdd(&d_deg_t[ei[Ee + i]], 1);
        }
        int t = threadIdx.x;
        ssum[t] = lsum; ssq[t] = lsq;
        __syncthreads();
        for (int s = 128; s > 0; s >>= 1) {
            if (t < s) { ssum[t] += ssum[t + s]; ssq[t] += ssq[t + s]; }
            __syncthreads();
        }
        if (t == 0) {
            atomicAdd(&d_stats[0], ssum[0]);
            atomicAdd(&d_stats[1], ssq[0]);
        }
    }
    grid_bar(2, SETUP_BLOCKS);

    if (blockIdx.x < 2) {
        int which = blockIdx.x;
        const int* deg = which ? d_deg_s : d_deg_t;
        int* off = which ? d_off_s : d_off_t;
        __shared__ int part[256];
        const int CH = (Nn + 255) / 256;
        int t = threadIdx.x;
        int s = 0;
        for (int i = 0; i < CH; i++) {
            int idx = t * CH + i;
            if (idx < Nn) s += deg[idx];
        }
        part[t] = s;
        __syncthreads();
        if (t == 0) {
            int run = 0;
            for (int i = 0; i < 256; i++) { int vv = part[i]; part[i] = run; run += vv; }
            off[Nn] = run;
        }
        __syncthreads();
        int run = part[t];
        for (int i = 0; i < CH; i++) {
            int idx = t * CH + i;
            if (idx < Nn) { off[idx] = run; run += deg[idx]; }
        }
    } else {
        float s = d_stats[0], sq = d_stats[1];
        float mean = s / (float)Ee;
        float var = (sq - s * s / (float)Ee) / (float)(Ee - 1);
        float inv = rsqrtf(var);
        int gg = (blockIdx.x - 2) * 256 + threadIdx.x;
        for (int i = gg; i < Ee; i += (SETUP_BLOCKS - 2) * 256)
            d_ea[i] = (ea[i] - mean) * inv;
    }
    grid_bar(3, SETUP_BLOCKS);

    for (int e = g; e < Ee; e += NT) {
        int sn = ei[e], tn = ei[Ee + e];
        int ps = atomicAdd(&d_cnt_s[sn], 1);
        int sslot = d_off_s[sn] + ps;
        int pt = atomicAdd(&d_cnt_t[tn], 1);
        int tslot = d_off_t[tn] + pt;
        d_sslot_t[tslot] = sslot;
        d_src_t[tslot] = sn;
        d_tgt_t[tslot] = tn;
        d_ea_t[tslot] = d_ea[e];
    }
}

// ---------------- per-node layer-1 precompute ----------------
__global__ void __launch_bounds__(256) upre_kernel(
    const float* __restrict__ feat,
    const float* __restrict__ w1, const float* __restrict__ b1, int t)
{
    __shared__ float sw[34 * 32];
    __shared__ float sb[32];
    for (int i = threadIdx.x; i < 34 * 32; i += 256) sw[i] = w1[i];
    if (threadIdx.x < 32) sb[threadIdx.x] = b1[threadIdx.x];
    __syncthreads();

    int row = blockIdx.x * 256 + threadIdx.x;
    if (row >= Bc * Nn) return;
    int b = row / Nn, n = row - b * Nn;

    float x[17];
    x[0] = d_xn[row];
    {
        const float4* fs = (const float4*)(feat + ((long long)(b * TT + HISTc + t) * Nn + n) * 16);
        float4 f0 = fs[0], f1 = fs[1], f2 = fs[2], f3 = fs[3];
        x[1] = f0.x; x[2] = f0.y; x[3] = f0.z; x[4] = f0.w;
        x[5] = f1.x; x[6] = f1.y; x[7] = f1.z; x[8] = f1.w;
        x[9] = f2.x; x[10] = f2.y; x[11] = f2.z; x[12] = f2.w;
        x[13] = f3.x; x[14] = f3.y; x[15] = f3.z; x[16] = f3.w;
    }

    float us[32], ut[32];
    #pragma unroll
    for (int j = 0; j < 32; j++) { us[j] = sb[j]; ut[j] = 0.f; }
    #pragma unroll
    for (int k = 0; k < 17; k++) {
        float xk = x[k];
        const float* ws = sw + k * 32;
        const float* wt = sw + (17 + k) * 32;
        #pragma unroll
        for (int j = 0; j < 32; j++) {
            us[j] = fmaf(xk, ws[j], us[j]);
            ut[j] = fmaf(xk, wt[j], ut[j]);
        }
    }
    uint32_t ps[16], pt[16];
    #pragma unroll
    for (int j = 0; j < 16; j++) {
        __half2 hs = __floats2half2_rn(us[2 * j], us[2 * j + 1]);
        __half2 ht = __floats2half2_rn(ut[2 * j], ut[2 * j + 1]);
        ps[j] = *(uint32_t*)&hs;
        pt[j] = *(uint32_t*)&ht;
    }
    uint4* dus = (uint4*)(d_us + (long long)row * 32);
    uint4* dut = (uint4*)(d_ut + (long long)row * 32);
    const uint4* psv = (const uint4*)ps;
    const uint4* ptv = (const uint4*)pt;
    #pragma unroll
    for (int q = 0; q < 4; q++) { dus[q] = psv[q]; dut[q] = ptv[q]; }
}

// ---------------- edge kernel: b-batched, coop gather/scatter + HMMA -------
// 128 threads = 4 warps; warp owns 32 consecutive t-slots; loops b = 0..7.
__global__ void __launch_bounds__(128) edge_kernel(
    const float* __restrict__ w1,
    const float* __restrict__ w2, const float* __restrict__ b2)
{
    __shared__ __align__(16) uint4 smA[4][128];   // message tile (swizzled)
    __shared__ __align__(16) uint4 smU[4][160];   // u_s stage, row stride 5
    __shared__ float s_w2[32 * 30];
    __shared__ float s_b2[32];
    __shared__ float s_wea[32];

    for (int i = threadIdx.x; i < 32 * 30; i += 128) s_w2[i] = w2[i];
    if (threadIdx.x < 32) {
        s_b2[threadIdx.x] = (threadIdx.x < 30) ? b2[threadIdx.x] : 0.f;
        s_wea[threadIdx.x] = w1[34 * 32 + threadIdx.x];
    }
    __syncthreads();

    int lane = threadIdx.x & 31;
    int w = threadIdx.x >> 5;
    int base = blockIdx.x * 128 + w * 32;    // warp's first t-slot
    int idx = base + lane;

    // ---- B fragments + bias (b-independent, built once) ----
    int kk = (lane & 3) * 2;
    int nn = lane >> 2;
    uint32_t bfr[4][2][2];
    float bias0[4], bias1[4];
    #pragma unroll
    for (int ni = 0; ni < 4; ni++) {
        int n0 = ni * 8 + nn;
        #pragma unroll
        for (int ki = 0; ki < 2; ki++) {
            int k0 = ki * 16 + kk;
            float f0 = (n0 < 30) ? s_w2[k0 * 30 + n0] : 0.f;
            float f1 = (n0 < 30) ? s_w2[(k0 + 1) * 30 + n0] : 0.f;
            float f2 = (n0 < 30) ? s_w2[(k0 + 8) * 30 + n0] : 0.f;
            float f3 = (n0 < 30) ? s_w2[(k0 + 9) * 30 + n0] : 0.f;
            __half2 h01 = __floats2half2_rn(f0, f1);
            __half2 h23 = __floats2half2_rn(f2, f3);
            bfr[ni][ki][0] = *(uint32_t*)&h01;
            bfr[ni][ki][1] = *(uint32_t*)&h23;
        }
        int c = ni * 8 + kk;
        bias0[ni] = s_b2[c];
        bias1[ni] = s_b2[c + 1];
    }

    // ---- indices loaded once, reused for all 8 batches ----
    int sn = d_src_t[idx], tn = d_tgt_t[idx];
    int ss = d_sslot_t[idx];
    float eav = d_ea_t[idx];

    for (int b = 0; b < Bc; b++) {
        // ---- cooperative u_s gather: 4 instr, 8 segments each ----
        {
            int j = lane & 3;          // 16B chunk
            int esub = lane >> 2;      // 0..7
            #pragma unroll
            for (int it = 0; it < 4; it++) {
                int e = it * 8 + esub;
                int sn_e = __shfl_sync(0xffffffffu, sn, e);
                smU[w][e * 5 + j] = ((const uint4*)(d_us + ((long long)b * Nn + sn_e) * 32))[j];
            }
        }
        // u_t per-thread (tgt-sorted: broadcast-heavy, cheap)
        uint4 utv[4];
        {
            const uint4* up = (const uint4*)(d_ut + ((long long)b * Nn + tn) * 32);
            #pragma unroll
            for (int q = 0; q < 4; q++) utv[q] = up[q];
        }
        __syncwarp();

        // ---- layer 1: read own u_s row from stage, sigmoid, pack fp16 ----
        uint4 hrow[4];
        #pragma unroll
        for (int q = 0; q < 4; q++) {
            uint4 va = smU[w][lane * 5 + q];
            uint4 vb = utv[q];
            const __half2* ha = (const __half2*)&va;
            const __half2* hb = (const __half2*)&vb;
            uint32_t packed[4];
            #pragma unroll
            for (int p = 0; p < 4; p++) {
                float2 fa = __half22float2(ha[p]);
                float2 fb = __half22float2(hb[p]);
                int c = q * 8 + p * 2;
                float v0 = sigm_fast(fmaf(eav, s_wea[c],     fa.x + fb.x));
                float v1 = sigm_fast(fmaf(eav, s_wea[c + 1], fa.y + fb.y));
                __half2 hv = __floats2half2_rn(v0, v1);
                packed[p] = *(uint32_t*)&hv;
            }
            hrow[q] = *(uint4*)packed;
        }

        // ---- STS h1 into swizzled tile ----
        {
            int sw = (lane >> 1) & 3;
            #pragma unroll
            for (int j = 0; j < 4; j++)
                smA[w][lane * 4 + (j ^ sw)] = hrow[j];
        }
        __syncwarp();

        // ---- ldmatrix A fragments ----
        uint32_t afr[2][2][4];
        {
            int grp = lane >> 3;
            int lr = lane & 7;
            #pragma unroll
            for (int mi = 0; mi < 2; mi++) {
                #pragma unroll
                for (int ki = 0; ki < 2; ki++) {
                    int row = mi * 16 + ((grp & 1) ? 8 : 0) + lr;
                    int chunk = ki * 2 + (grp >> 1);
                    int phys = row * 4 + (chunk ^ ((row >> 1) & 3));
                    uint32_t addr = smem_u32(&smA[w][phys]);
                    asm volatile("ldmatrix.sync.aligned.m8n8.x4.shared.b16 {%0,%1,%2,%3}, [%4];"
                                 : "=r"(afr[mi][ki][0]), "=r"(afr[mi][ki][1]),
                                   "=r"(afr[mi][ki][2]), "=r"(afr[mi][ki][3])
                                 : "r"(addr));
                }
            }
        }

        // ---- 16 MMAs ----
        float dacc[2][4][4];
        #pragma unroll
        for (int mi = 0; mi < 2; mi++)
            #pragma unroll
            for (int ni = 0; ni < 4; ni++)
                #pragma unroll
                for (int p = 0; p < 4; p++) dacc[mi][ni][p] = 0.f;
        #pragma unroll
        for (int mi = 0; mi < 2; mi++) {
            #pragma unroll
            for (int ni = 0; ni < 4; ni++) {
                #pragma unroll
                for (int ki = 0; ki < 2; ki++) {
                    asm volatile(
                        "mma.sync.aligned.m16n8k16.row.col.f32.f16.f16.f32 "
                        "{%0,%1,%2,%3}, {%4,%5,%6,%7}, {%8,%9}, {%0,%1,%2,%3};"
                        : "+f"(dacc[mi][ni][0]), "+f"(dacc[mi][ni][1]),
                          "+f"(dacc[mi][ni][2]), "+f"(dacc[mi][ni][3])
                        : "r"(afr[mi][ki][0]), "r"(afr[mi][ki][1]),
                          "r"(afr[mi][ki][2]), "r"(afr[mi][ki][3]),
                          "r"(bfr[ni][ki][0]), "r"(bfr[ni][ki][1]));
                }
            }
        }
        __syncwarp();

        // ---- epilogue: bias + sigmoid -> swizzled tile ----
        {
            uint32_t* u = (uint32_t*)&smA[w][0];
            int gr = lane >> 2;
            #pragma unroll
            for (int mi = 0; mi < 2; mi++) {
                #pragma unroll
                for (int ni = 0; ni < 4; ni++) {
                    float v0 = sigm_fast(dacc[mi][ni][0] + bias0[ni]);
                    float v1 = sigm_fast(dacc[mi][ni][1] + bias1[ni]);
                    float v2 = sigm_fast(dacc[mi][ni][2] + bias0[ni]);
                    float v3 = sigm_fast(dacc[mi][ni][3] + bias1[ni]);
                    __half2 h01 = __floats2half2_rn(v0, v1);
                    __half2 h23 = __floats2half2_rn(v2, v3);
                    int row0 = mi * 16 + gr;
                    int row1 = row0 + 8;
                    int c0 = ni ^ ((row0 >> 1) & 3);
                    int c1 = ni ^ ((row1 >> 1) & 3);
                    u[(row0 * 4 + c0) * 4 + (lane & 3)] = *(uint32_t*)&h01;
                    u[(row1 * 4 + c1) * 4 + (lane & 3)] = *(uint32_t*)&h23;
                }
            }
        }
        __syncwarp();

        // ---- cooperative dual store from tile: 4 instr each, pad zeroed ----
        {
            int j = lane & 3;
            int esub = lane >> 2;
            #pragma unroll
            for (int it = 0; it < 4; it++) {
                int e = it * 8 + esub;
                uint4 v = smA[w][e * 4 + (j ^ ((e >> 1) & 3))];
                if (j == 3) v.w = 0u;    // channels 30,31
                int ss_e = __shfl_sync(0xffffffffu, ss, e);
                ((uint4*)(d_hbuf_t + ((long long)b * Ee + base + e) * 32))[j] = v;
                ((uint4*)(d_hbuf_s + ((long long)b * Ee + ss_e) * 32))[j] = v;
            }
        }
    }
}

// ---------------- persistent step2: 2 rows per warp, vectorized gather -----
static constexpr int S2_BLOCKS = 296;
static constexpr int S2_WARPS  = 16;     // 512 threads
static constexpr int TASKS = Bc * Nn / 2;  // 40000

__global__ void __launch_bounds__(512) step2_kernel(
    const float* __restrict__ feat,
    const float* __restrict__ node_w, const float* __restrict__ node_b,
    const float* __restrict__ bih, const float* __restrict__ bhh,
    const float* __restrict__ fcw, const float* __restrict__ fcb,
    float* __restrict__ out, int t)
{
    extern __shared__ float dynw[];
    float2* s_wih2 = (float2*)dynw;                 // [30][96] pairs
    float2* s_whh2 = (float2*)(dynw + 30 * 96 * 2); // [64][96] pairs
    __shared__ __align__(16) float sx[S2_WARPS][2][32];
    __shared__ __align__(16) float sxin[S2_WARPS][2][32];
    __shared__ __align__(16) float sh[S2_WARPS][128];
    __shared__ float s_nw[30 * 13], s_nb[16];

    for (int i = threadIdx.x; i < 30 * 96; i += 512) s_wih2[i] = d_wihT2[i];
    for (int i = threadIdx.x; i < 64 * 96; i += 512) s_whh2[i] = d_whhT2[i];
    for (int i = threadIdx.x; i < 30 * 13; i += 512) s_nw[i] = node_w[i];
    if (threadIdx.x < 13) s_nb[threadIdx.x] = node_b[threadIdx.x];
    __syncthreads();

    int lane = threadIdx.x & 31;
    int w = threadIdx.x >> 5;
    float* shp = sh[w];
    int sub = lane >> 2;

    unsigned long long bih_r = pack2(bih[lane],       bih[32 + lane]);
    unsigned long long bih_z = pack2(bih[64 + lane],  bih[96 + lane]);
    unsigned long long bih_n = pack2(bih[128 + lane], bih[160 + lane]);
    unsigned long long bhh_r = pack2(bhh[lane],       bhh[32 + lane]);
    unsigned long long bhh_z = pack2(bhh[64 + lane],  bhh[96 + lane]);
    unsigned long long bhh_n = pack2(bhh[128 + lane], bhh[160 + lane]);
    float fcw0 = fcw[lane], fcw1 = fcw[32 + lane];
    float fcb0 = fcb[0];

    for (int task = blockIdx.x * S2_WARPS + w; task < TASKS; task += S2_BLOCKS * S2_WARPS) {
        int row0 = task * 2;
        int b = row0 / Nn, n0 = row0 - b * Nn;

        #pragma unroll
        for (int r = 0; r < 2; r++) {
            int n = n0 + r;
            float2 acc[4];
            #pragma unroll
            for (int p = 0; p < 4; p++) acc[p] = make_float2(0.f, 0.f);
            {
                int e0 = d_off_t[n], e1 = d_off_t[n + 1];
                int cnt = e1 - e0;
                const uint4* p4 = (const uint4*)(d_hbuf_t + ((long long)b * Ee + e0) * 32);
                int full = cnt >> 3, tail = cnt & 7;
                for (int i = 0; i < full; i++) {
                    uint4 v = p4[i * 32 + lane];
                    const __half2* h = (const __half2*)&v;
                    #pragma unroll
                    for (int p = 0; p < 4; p++) {
                        float2 f = __half22float2(h[p]);
                        acc[p].x += f.x; acc[p].y += f.y;
                    }
                }
                if (sub < tail) {
                    uint4 v = p4[full * 32 + lane];
                    const __half2* h = (const __half2*)&v;
                    #pragma unroll
                    for (int p = 0; p < 4; p++) {
                        float2 f = __half22float2(h[p]);
                        acc[p].x += f.x; acc[p].y += f.y;
                    }
                }
            }
            {
                int e0 = d_off_s[n], e1 = d_off_s[n + 1];
                int cnt = e1 - e0;
                const uint4* p4 = (const uint4*)(d_hbuf_s + ((long long)b * Ee + e0) * 32);
                int full = cnt >> 3, tail = cnt & 7;
                for (int i = 0; i < full; i++) {
                    uint4 v = p4[i * 32 + lane];
                    const __half2* h = (const __half2*)&v;
                    #pragma unroll
                    for (int p = 0; p < 4; p++) {
                        float2 f = __half22float2(h[p]);
                        acc[p].x -= f.x; acc[p].y -= f.y;
                    }
                }
                if (sub < tail) {
                    uint4 v = p4[full * 32 + lane];
                    const __half2* h = (const __half2*)&v;
                    #pragma unroll
                    for (int p = 0; p < 4; p++) {
                        float2 f = __half22float2(h[p]);
                        acc[p].x -= f.x; acc[p].y -= f.y;
                    }
                }
            }
            #pragma unroll
            for (int p = 0; p < 4; p++) {
                #pragma unroll
                for (int st = 4; st <= 16; st <<= 1) {
                    acc[p].x += __shfl_xor_sync(0xffffffffu, acc[p].x, st);
                    acc[p].y += __shfl_xor_sync(0xffffffffu, acc[p].y, st);
                }
            }
            if (lane < 4) {
                float2* sxf2 = (float2*)sx[w][r];
                #pragma unroll
                for (int p = 0; p < 4; p++) sxf2[lane * 4 + p] = acc[p];
            }
        }
        __syncwarp();

        if (lane < 26) {
            int r = (lane >= 13) ? 1 : 0;
            int u = lane - 13 * r;
            float g = s_nb[u];
            #pragma unroll
            for (int k = 0; k < 30; k++) g = fmaf(sx[w][r][k], s_nw[k * 13 + u], g);
            sxin[w][r][u] = sigm(g);
        }
        if (lane < 2) sxin[w][lane][13] = d_xn[row0 + lane];
        #pragma unroll
        for (int r = 0; r < 2; r++) {
            if (lane < 16)
                sxin[w][r][14 + lane] = feat[((long long)(b * TT + HISTc + t) * Nn + n0 + r) * 16 + lane];
        }
        ((float4*)shp)[lane] = ((const float4*)(d_h + (long long)row0 * 64))[lane];
        __syncwarp();

        unsigned long long ar0 = bih_r, az0 = bih_z, an0 = bih_n;
        unsigned long long ar1 = bih_r, az1 = bih_z, an1 = bih_n;
        #pragma unroll
        for (int k = 0; k < 30; k++) {
            const unsigned long long* wr = (const unsigned long long*)(s_wih2 + k * 96);
            unsigned long long wR = wr[lane], wZ = wr[32 + lane], wN = wr[64 + lane];
            unsigned long long x0 = splat2(sxin[w][0][k]);
            unsigned long long x1 = splat2(sxin[w][1][k]);
            fma2(ar0, x0, wR); fma2(az0, x0, wZ); fma2(an0, x0, wN);
            fma2(ar1, x1, wR); fma2(az1, x1, wZ); fma2(an1, x1, wN);
        }
        unsigned long long gr0 = bhh_r, gz0 = bhh_z, gn0 = bhh_n;
        unsigned long long gr1 = bhh_r, gz1 = bhh_z, gn1 = bhh_n;
        #pragma unroll
        for (int k = 0; k < 64; k++) {
            const unsigned long long* wr = (const unsigned long long*)(s_whh2 + k * 96);
            unsigned long long wR = wr[lane], wZ = wr[32 + lane], wN = wr[64 + lane];
            unsigned long long h0 = splat2(shp[k]);
            unsigned long long h1 = splat2(shp[64 + k]);
            fma2(gr0, h0, wR); fma2(gz0, h0, wZ); fma2(gn0, h0, wN);
            fma2(gr1, h1, wR); fma2(gz1, h1, wZ); fma2(gn1, h1, wN);
        }

        {
            float2 fa_r = unpack2(ar0), fa_z = unpack2(az0), fa_n = unpack2(an0);
            float2 fg_r = unpack2(gr0), fg_z = unpack2(gz0), fg_n = unpack2(gn0);
            float hold0 = shp[lane], hold1 = shp[32 + lane];
            float r0 = sigm(fa_r.x + fg_r.x), r1 = sigm(fa_r.y + fg_r.y);
            float z0 = sigm(fa_z.x + fg_z.x), z1 = sigm(fa_z.y + fg_z.y);
            float nn0 = tanh_f(fa_n.x + r0 * fg_n.x), nn1 = tanh_f(fa_n.y + r1 * fg_n.y);
            float hn0 = (1.f - z0) * nn0 + z0 * hold0;
            float hn1 = (1.f - z1) * nn1 + z1 * hold1;
            long long rw = (long long)row0 * 64;
            d_h[rw + lane] = hn0;
            d_h[rw + 32 + lane] = hn1;
            float o = hn0 * fcw0 + hn1 * fcw1;
            #pragma unroll
            for (int off = 16; off > 0; off >>= 1)
                o += __shfl_xor_sync(0xffffffffu, o, off);
            if (lane == 0) {
                float v = o + fcb0;
                d_xn[row0] = v;
                out[((long long)b * PREDc + t) * Nn + n0] = v;
            }
        }
        {
            float2 fa_r = unpack2(ar1), fa_z = unpack2(az1), fa_n = unpack2(an1);
            float2 fg_r = unpack2(gr1), fg_z = unpack2(gz1), fg_n = unpack2(gn1);
            float hold0 = shp[64 + lane], hold1 = shp[96 + lane];
            float r0 = sigm(fa_r.x + fg_r.x), r1 = sigm(fa_r.y + fg_r.y);
            float z0 = sigm(fa_z.x + fg_z.x), z1 = sigm(fa_z.y + fg_z.y);
            float nn0 = tanh_f(fa_n.x + r0 * fg_n.x), nn1 = tanh_f(fa_n.y + r1 * fg_n.y);
            float hn0 = (1.f - z0) * nn0 + z0 * hold0;
            float hn1 = (1.f - z1) * nn1 + z1 * hold1;
            long long rw = (long long)(row0 + 1) * 64;
            d_h[rw + lane] = hn0;
            d_h[rw + 32 + lane] = hn1;
            float o = hn0 * fcw0 + hn1 * fcw1;
            #pragma unroll
            for (int off = 16; off > 0; off >>= 1)
                o += __shfl_xor_sync(0xffffffffu, o, off);
            if (lane == 0) {
                float v = o + fcb0;
                d_xn[row0 + 1] = v;
                out[((long long)b * PREDc + t) * Nn + n0 + 1] = v;
            }
        }
        __syncwarp();
    }
}

// ---------------- launcher ----------------
extern "C" void kernel_launch(void* const* d_in, const int* in_sizes, int n_in,
                              void* d_out, int out_size)
{
    const float* t2m  = (const float*)d_in[0];
    const float* feat = (const float*)d_in[1];
    const int*   ei   = (const int*)d_in[2];
    const float* ea   = (const float*)d_in[3];
    const float* w1   = (const float*)d_in[4];
    const float* b1   = (const float*)d_in[5];
    const float* w2   = (const float*)d_in[6];
    const float* b2   = (const float*)d_in[7];
    const float* nw   = (const float*)d_in[8];
    const float* nb   = (const float*)d_in[9];
    const float* wih  = (const float*)d_in[10];
    const float* whh  = (const float*)d_in[11];
    const float* bih  = (const float*)d_in[12];
    const float* bhh  = (const float*)d_in[13];
    const float* fcw  = (const float*)d_in[14];
    const float* fcb  = (const float*)d_in[15];
    float* out = (float*)d_out;

    const int smem2 = (30 * 96 + 64 * 96) * 2 * (int)sizeof(float);
    cudaFuncSetAttribute(step2_kernel, cudaFuncAttributeMaxDynamicSharedMemorySize, smem2);

    // launches: reset(0), setup(1), upre(2), edge(3) <- ncu profiles index 3
    reset_bar_kernel<<<1, 32>>>();
    setup_kernel<<<SETUP_BLOCKS, 256>>>(t2m, ea, ei, wih, whh);

    for (int t = 0; t < PREDc; t++) {
        upre_kernel<<<(Bc * Nn + 255) / 256, 256>>>(feat, w1, b1, t);
        edge_kernel<<<Ee / 128, 128>>>(w1, w2, b2);
        step2_kernel<<<S2_BLOCKS, 512, smem2>>>(feat, nw, nb, bih, bhh, fcw, fcb, out, t);
    }
}